// round 2
// baseline (speedup 1.0000x reference)
#include <cuda_runtime.h>
#include <math.h>

#define DIMD 1024
#define BQ   4
#define SEQ  2048
#define RR   3
#define KKC  256
#define MAXR 256
#define NH   8
#define HDIM 128

// ---------------- scratch (device globals; no allocs allowed) ----------------
constexpr size_t SZ_QF   = (size_t)RR*BQ*SEQ*DIMD;   // 25165824
constexpr size_t SZ_ROW  = (size_t)BQ*SEQ*DIMD;      // 8388608
constexpr size_t SZ_SC   = (size_t)RR*BQ*SEQ*SEQ;    // 50331648
constexpr size_t SZ_ATT  = (size_t)BQ*NH*SEQ*MAXR;   // 16777216
constexpr size_t SZ_HBUF = (size_t)RR*BQ*KKC*512;    // 1572864
constexpr size_t SZ_SEL  = (size_t)BQ*MAXR*DIMD;     // 1048576
constexpr size_t SZ_RBV  = (size_t)RR*BQ*SEQ;        // 24576

constexpr size_t OFF_QF     = 0;
constexpr size_t OFF_TMP    = OFF_QF   + SZ_QF;
constexpr size_t OFF_SC     = OFF_TMP  + SZ_ROW;
constexpr size_t OFF_QP     = OFF_SC   + SZ_SC;
constexpr size_t OFF_AO     = OFF_QP   + SZ_ROW;
constexpr size_t OFF_FUSED  = OFF_AO   + SZ_ROW;
constexpr size_t OFF_ATT    = OFF_FUSED+ SZ_ROW;
constexpr size_t OFF_HBUF   = OFF_ATT  + SZ_ATT;
constexpr size_t OFF_SEL    = OFF_HBUF + SZ_HBUF;
constexpr size_t OFF_KP     = OFF_SEL  + SZ_SEL;
constexpr size_t OFF_VP     = OFF_KP   + SZ_SEL;
constexpr size_t OFF_RINV   = OFF_VP   + SZ_SEL;
constexpr size_t OFF_W      = OFF_RINV + SZ_RBV;
constexpr size_t OFF_POOLED = OFF_W    + SZ_RBV;
constexpr size_t OFF_PLN    = OFF_POOLED + (size_t)RR*BQ*DIMD;
constexpr size_t OFF_QUER   = OFF_PLN    + (size_t)RR*BQ*DIMD;
constexpr size_t OFF_QC     = OFF_QUER   + (size_t)RR*BQ*DIMD;
constexpr size_t OFF_REL    = OFF_QC     + (size_t)RR*BQ*512;
constexpr size_t SCRATCH_TOTAL = OFF_REL + (size_t)RR*BQ*KKC;

__device__ float g_scratch[SCRATCH_TOTAL];
__device__ int   g_topidx[BQ*MAXR];
__device__ int   g_keyvalid[BQ*MAXR];
__device__ int   g_anyvalid[BQ];

// ---------------- helpers ----------------
__device__ __forceinline__ float gelu_f(float v){
    return 0.5f*v*(1.0f + erff(v*0.7071067811865475f));
}

__device__ __forceinline__ float bsum(float v){
    __shared__ float sh[32]; __shared__ float total;
    int lane = threadIdx.x & 31, w = threadIdx.x >> 5;
    #pragma unroll
    for (int o=16;o;o>>=1) v += __shfl_down_sync(0xffffffffu, v, o);
    __syncthreads();
    if (lane==0) sh[w] = v;
    __syncthreads();
    if (w==0){
        int nw = blockDim.x >> 5;
        float t = (lane < nw) ? sh[lane] : 0.f;
        #pragma unroll
        for (int o=16;o;o>>=1) t += __shfl_down_sync(0xffffffffu, t, o);
        if (lane==0) total = t;
    }
    __syncthreads();
    return total;
}

__device__ __forceinline__ float bmax(float v){
    __shared__ float sh[32]; __shared__ float total;
    int lane = threadIdx.x & 31, w = threadIdx.x >> 5;
    #pragma unroll
    for (int o=16;o;o>>=1) v = fmaxf(v, __shfl_down_sync(0xffffffffu, v, o));
    __syncthreads();
    if (lane==0) sh[w] = v;
    __syncthreads();
    if (w==0){
        int nw = blockDim.x >> 5;
        float t = (lane < nw) ? sh[lane] : -INFINITY;
        #pragma unroll
        for (int o=16;o;o>>=1) t = fmaxf(t, __shfl_down_sync(0xffffffffu, t, o));
        if (lane==0) total = t;
    }
    __syncthreads();
    return total;
}

// ---------------- generic batched SGEMM: C = act(alpha*A@B(^T) + bias) ----------------
// 64x64x16 tile, 256 threads, 4x4 microtile, padded smem, float4 LDS.
#define GBM 64
#define GBN 64
#define GBK 16

__global__ void gemm_kernel(const float* __restrict__ A, const float* __restrict__ Bm,
                            const float* __restrict__ bias, float* __restrict__ C,
                            int M, int N, int K, int lda, int ldb, int ldc,
                            long long sA1, long long sB1, long long sC1,
                            int batch2,
                            long long sA2, long long sB2, long long sC2,
                            float alpha, int transB, int act)
{
    int z = blockIdx.z;
    int b1 = z / batch2, b2 = z % batch2;
    A  += b1*sA1 + b2*sA2;
    Bm += b1*sB1 + b2*sB2;
    C  += b1*sC1 + b2*sC2;

    __shared__ __align__(16) float As[GBK][GBM+4];
    __shared__ __align__(16) float Bs[GBK][GBN+4];

    int tid = threadIdx.x;
    int tx = tid & 15, ty = tid >> 4;
    int m0 = blockIdx.y * GBM, n0 = blockIdx.x * GBN;

    float acc[4][4] = {};

    for (int k0 = 0; k0 < K; k0 += GBK){
        // A tile: read coalesced along k, store transposed [kk][mm]
        #pragma unroll
        for (int i = tid; i < GBM*GBK; i += 256){
            int mm = i >> 4, kk = i & 15;
            int gm = m0 + mm, gk = k0 + kk;
            As[kk][mm] = (gm < M) ? A[(long long)gm*lda + gk] : 0.f;
        }
        if (!transB){
            #pragma unroll
            for (int i = tid; i < GBK*GBN; i += 256){
                int kk = i >> 6, nn = i & 63;
                int gk = k0 + kk, gn = n0 + nn;
                Bs[kk][nn] = (gn < N) ? Bm[(long long)gk*ldb + gn] : 0.f;
            }
        } else {
            #pragma unroll
            for (int i = tid; i < GBK*GBN; i += 256){
                int nn = i >> 4, kk = i & 15;
                int gk = k0 + kk, gn = n0 + nn;
                Bs[kk][nn] = (gn < N) ? Bm[(long long)gn*ldb + gk] : 0.f;
            }
        }
        __syncthreads();

        #pragma unroll
        for (int kk = 0; kk < GBK; kk++){
            float4 av = *reinterpret_cast<const float4*>(&As[kk][ty*4]);
            float4 bv = *reinterpret_cast<const float4*>(&Bs[kk][tx*4]);
            float a[4] = {av.x, av.y, av.z, av.w};
            float b[4] = {bv.x, bv.y, bv.z, bv.w};
            #pragma unroll
            for (int i=0;i<4;i++)
                #pragma unroll
                for (int j=0;j<4;j++)
                    acc[i][j] += a[i]*b[j];
        }
        __syncthreads();
    }

    #pragma unroll
    for (int i=0;i<4;i++){
        int gm = m0 + ty*4 + i;
        if (gm >= M) continue;
        #pragma unroll
        for (int j=0;j<4;j++){
            int gn = n0 + tx*4 + j;
            if (gn >= N) continue;
            float v = acc[i][j]*alpha;
            if (bias) v += bias[gn];
            if (act == 1) v = gelu_f(v);
            C[(long long)gm*ldc + gn] = v;
        }
    }
}

// ---------------- pooling softmax (in-place exp, store 1/Z) ----------------
__global__ void softmax_rows_kernel(float* __restrict__ sc, float* __restrict__ rinv){
    long long row = blockIdx.x;
    float* p = sc + row*SEQ;
    float m = -INFINITY;
    for (int t=threadIdx.x; t<SEQ; t+=256) m = fmaxf(m, p[t]);
    m = bmax(m);
    float z = 0.f;
    for (int t=threadIdx.x; t<SEQ; t+=256){ float e = __expf(p[t]-m); p[t]=e; z += e; }
    z = bsum(z);
    if (threadIdx.x==0) rinv[row] = 1.0f/z;
}

// w[rb][t] = (1/S) * sum_s P[s][t] * rinv[s]
__global__ void colw_kernel(const float* __restrict__ sc, const float* __restrict__ rinv,
                            float* __restrict__ w){
    int rb = blockIdx.y;
    int t  = blockIdx.x*128 + threadIdx.x;
    const float* p  = sc + (long long)rb*SEQ*SEQ + t;
    const float* ri = rinv + rb*SEQ;
    float acc = 0.f;
    for (int s=0; s<SEQ; s++) acc += p[(long long)s*SEQ] * ri[s];
    w[rb*SEQ + t] = acc * (1.0f/(float)SEQ);
}

// pooled[rb][d] = sum_t w[rb][t] * qf[rb][t][d]
__global__ void pooled_kernel(const float* __restrict__ qf, const float* __restrict__ w,
                              float* __restrict__ pooled){
    int rb = blockIdx.y;
    int d  = blockIdx.x*256 + threadIdx.x;
    const float* q  = qf + (long long)rb*SEQ*DIMD + d;
    const float* wp = w + rb*SEQ;
    float acc = 0.f;
    for (int t=0; t<SEQ; t++) acc += wp[t]*q[(long long)t*DIMD];
    pooled[rb*DIMD + d] = acc;
}

// LayerNorm over 1024, per-r gamma/beta
__global__ void lnvec_kernel(const float* __restrict__ in, const float* __restrict__ g,
                             const float* __restrict__ b_, float* __restrict__ out){
    int rb = blockIdx.x; int r = rb / BQ;
    const float* p = in + rb*DIMD;
    float s = 0.f;
    for (int i=threadIdx.x;i<DIMD;i+=256) s += p[i];
    float mean = bsum(s)*(1.0f/DIMD);
    float v = 0.f;
    for (int i=threadIdx.x;i<DIMD;i+=256){ float d=p[i]-mean; v += d*d; }
    float var = bsum(v)*(1.0f/DIMD);
    float rs = rsqrtf(var + 1e-5f);
    for (int i=threadIdx.x;i<DIMD;i+=256)
        out[rb*DIMD+i] = (p[i]-mean)*rs*g[r*DIMD+i] + b_[r*DIMD+i];
}

// out[rb][e] = sum_d vin[rb][d] * W[r*wstride + (Koff+d)*N + e] + bias[r*bstride + e]
__global__ void gemv_rb_kernel(const float* __restrict__ vin, const float* __restrict__ W,
                               const float* __restrict__ bias, float* __restrict__ out,
                               int N, int Koff, long long wstride, int bstride){
    int rb = blockIdx.y; int r = rb / BQ;
    int e = blockIdx.x*256 + threadIdx.x;
    __shared__ float sv[DIMD];
    for (int i=threadIdx.x;i<DIMD;i+=256) sv[i] = vin[rb*DIMD+i];
    __syncthreads();
    const float* Wp = W + (long long)r*wstride + (long long)Koff*N;
    if (e < N){
        float acc = 0.f;
        for (int d=0; d<DIMD; d++) acc += sv[d]*Wp[(long long)d*N + e];
        out[rb*N + e] = acc + bias[r*bstride + e];
    }
}

// rel[rbk] = sigmoid( sum_n gelu(h[rbk][n] + qc[rb][n]) * w2[n] + b2 )
__global__ void rel_kernel(const float* __restrict__ hbuf, const float* __restrict__ qc,
                           const float* __restrict__ w2, const float* __restrict__ b2,
                           float* __restrict__ rel){
    int row = blockIdx.x; int rb = row >> 8;
    const float* hp = hbuf + (long long)row*512;
    const float* qp = qc + rb*512;
    float acc = 0.f;
    for (int n=threadIdx.x; n<512; n+=256)
        acc += gelu_f(hp[n] + qp[n]) * w2[n];
    acc = bsum(acc);
    if (threadIdx.x==0) rel[row] = 1.0f/(1.0f + __expf(-(acc + b2[0])));
}

// per-batch threshold + stable top-256 of the 768 candidates (bitonic over 1024)
__global__ void topk_kernel(const float* __restrict__ rel, int* __restrict__ topidx,
                            int* __restrict__ keyvalid, int* __restrict__ anyvalid){
    int b = blockIdx.x;
    __shared__ float v[1024];
    __shared__ int   id[1024];
    for (int i=threadIdx.x; i<1024; i+=256){
        if (i < RR*KKC){
            int r = i >> 8, k = i & 255;
            float s = rel[(r*BQ + b)*KKC + k];
            v[i]  = (s >= 0.5f) ? s : -INFINITY;
            id[i] = i;
        } else { v[i] = -INFINITY; id[i] = 1<<20; }
    }
    __syncthreads();
    for (int k=2; k<=1024; k<<=1){
        for (int j=k>>1; j>0; j>>=1){
            for (int i=threadIdx.x; i<1024; i+=256){
                int ixj = i ^ j;
                if (ixj > i){
                    float vi=v[i], vj=v[ixj]; int ii=id[i], ij=id[ixj];
                    bool before = (vi > vj) || (vi == vj && ii < ij);  // desired: val desc, idx asc
                    bool dir = ((i & k) == 0);
                    if (before != dir){ v[i]=vj; v[ixj]=vi; id[i]=ij; id[ixj]=ii; }
                }
            }
            __syncthreads();
        }
    }
    for (int j=threadIdx.x; j<MAXR; j+=256){
        topidx[b*MAXR + j]   = id[j];
        keyvalid[b*MAXR + j] = (v[j] >= 0.5f) ? 1 : 0;
    }
    if (threadIdx.x==0) anyvalid[b] = (v[0] >= 0.5f) ? 1 : 0;
}

__global__ void gather_kernel(const float* __restrict__ retrieved, const int* __restrict__ topidx,
                              float* __restrict__ sel){
    int b = blockIdx.y, j = blockIdx.x;
    int c = topidx[b*MAXR + j];
    int r = c >> 8, k = c & 255;
    const float* src = retrieved + (((long long)(r*BQ + b))*KKC + k)*DIMD;
    float* dst = sel + ((long long)(b*MAXR + j))*DIMD;
    for (int d=threadIdx.x; d<DIMD; d+=256) dst[d] = src[d];
}

// mask + softmax over the 256 selected keys, in place
__global__ void attn_softmax_kernel(float* __restrict__ att, const int* __restrict__ keyvalid){
    int s = blockIdx.x, h = blockIdx.y, b = blockIdx.z;
    float* p = att + ((((long long)b*NH + h)*SEQ) + s)*MAXR;
    int t = threadIdx.x;
    float val = p[t];
    if (!keyvalid[b*MAXR + t]) val = -1e9f;
    float m = bmax(val);
    float e = __expf(val - m);
    float z = bsum(e);
    p[t] = e / z;
}

// residual + LayerNorm + per-batch select
__global__ void final_kernel(const float* __restrict__ x, const float* __restrict__ fused,
                             const float* __restrict__ g, const float* __restrict__ bb,
                             const int* __restrict__ anyvalid, float* __restrict__ out){
    long long row = blockIdx.x;
    int b = (int)(row >> 11);
    const float* xp = x + row*DIMD;
    const float* fp = fused + row*DIMD;
    float* op = out + row*DIMD;
    bool any = anyvalid[b] != 0;
    float yv[4]; float s = 0.f;
    #pragma unroll
    for (int i=0;i<4;i++){ int idx = threadIdx.x + i*256; yv[i] = xp[idx] + fp[idx]; s += yv[i]; }
    float mean = bsum(s)*(1.0f/DIMD);
    float v = 0.f;
    #pragma unroll
    for (int i=0;i<4;i++){ float d = yv[i]-mean; v += d*d; }
    float var = bsum(v)*(1.0f/DIMD);
    float rs = rsqrtf(var + 1e-5f);
    #pragma unroll
    for (int i=0;i<4;i++){
        int idx = threadIdx.x + i*256;
        op[idx] = any ? ((yv[i]-mean)*rs*g[idx] + bb[idx]) : xp[idx];
    }
}

// ---------------- host ----------------
static void gemm(const float* A, const float* B, const float* bias, float* C,
                 int M, int N, int K, int lda, int ldb, int ldc,
                 int nb, long long sA1, long long sB1, long long sC1,
                 int b2, long long sA2, long long sB2, long long sC2,
                 float alpha, int transB, int act)
{
    dim3 grid((N+GBN-1)/GBN, (M+GBM-1)/GBM, nb);
    gemm_kernel<<<grid, 256>>>(A,B,bias,C,M,N,K,lda,ldb,ldc,
                               sA1,sB1,sC1,b2,sA2,sB2,sC2,alpha,transB,act);
}

extern "C" void kernel_launch(void* const* d_in, const int* in_sizes, int n_in,
                              void* d_out, int out_size)
{
    const float* x       = (const float*)d_in[0];
    const float* retr    = (const float*)d_in[1];
    const float* qg_w1   = (const float*)d_in[2];
    const float* qg_b1   = (const float*)d_in[3];
    const float* qg_w2   = (const float*)d_in[4];
    const float* qg_b2   = (const float*)d_in[5];
    const float* pln_g   = (const float*)d_in[6];
    const float* pln_b   = (const float*)d_in[7];
    const float* pool_w  = (const float*)d_in[8];
    const float* pool_b  = (const float*)d_in[9];
    const float* rel_w1  = (const float*)d_in[10];
    const float* rel_b1  = (const float*)d_in[11];
    const float* rel_w2  = (const float*)d_in[12];
    const float* rel_b2  = (const float*)d_in[13];
    const float* in_w    = (const float*)d_in[14];
    const float* in_b    = (const float*)d_in[15];
    const float* out_w   = (const float*)d_in[16];
    const float* out_b   = (const float*)d_in[17];
    const float* fln_g   = (const float*)d_in[18];
    const float* fln_b   = (const float*)d_in[19];

    float* S = nullptr;
    cudaGetSymbolAddress((void**)&S, g_scratch);
    int *TI=nullptr, *KV=nullptr, *AV=nullptr;
    cudaGetSymbolAddress((void**)&TI, g_topidx);
    cudaGetSymbolAddress((void**)&KV, g_keyvalid);
    cudaGetSymbolAddress((void**)&AV, g_anyvalid);

    float* QF     = S + OFF_QF;
    float* TMP    = S + OFF_TMP;
    float* SC     = S + OFF_SC;
    float* QP     = S + OFF_QP;
    float* AO     = S + OFF_AO;
    float* FUSED  = S + OFF_FUSED;
    float* ATT    = S + OFF_ATT;
    float* HBUF   = S + OFF_HBUF;
    float* SEL    = S + OFF_SEL;
    float* KP     = S + OFF_KP;
    float* VP     = S + OFF_VP;
    float* RINV   = S + OFF_RINV;
    float* WCOL   = S + OFF_W;
    float* POOLED = S + OFF_POOLED;
    float* PLN    = S + OFF_PLN;
    float* QUER   = S + OFF_QUER;
    float* QC     = S + OFF_QC;
    float* REL    = S + OFF_REL;

    const int MS = BQ*SEQ;  // 8192

    // ---- Stage A: per-retriever query-gen MLP -> QF[r] ----
    for (int r = 0; r < RR; r++){
        gemm(x, qg_w1 + (size_t)r*DIMD*DIMD, qg_b1 + (size_t)r*DIMD, TMP,
             MS, DIMD, DIMD, DIMD, DIMD, DIMD,
             1, 0,0,0, 1, 0,0,0, 1.0f, 0, 1);
        gemm(TMP, qg_w2 + (size_t)r*DIMD*DIMD, qg_b2 + (size_t)r*DIMD, QF + (size_t)r*MS*DIMD,
             MS, DIMD, DIMD, DIMD, DIMD, DIMD,
             1, 0,0,0, 1, 0,0,0, 1.0f, 0, 0);
    }

    // ---- Stage B: pooling attention scores = qf @ qf^T / 32, batched over 12 (r,b) ----
    gemm(QF, QF, nullptr, SC,
         SEQ, SEQ, DIMD, DIMD, DIMD, SEQ,
         RR*BQ, (long long)SEQ*DIMD, (long long)SEQ*DIMD, (long long)SEQ*SEQ,
         1, 0,0,0, 1.0f/32.0f, 1, 0);

    // ---- Stage C: row softmax (in place) + column weights ----
    softmax_rows_kernel<<<RR*BQ*SEQ, 256>>>(SC, RINV);
    colw_kernel<<<dim3(SEQ/128, RR*BQ), 128>>>(SC, RINV, WCOL);

    // ---- Stage D: pooled -> LN -> queries ----
    pooled_kernel<<<dim3(DIMD/256, RR*BQ), 256>>>(QF, WCOL, POOLED);
    lnvec_kernel<<<RR*BQ, 256>>>(POOLED, pln_g, pln_b, PLN);
    gemv_rb_kernel<<<dim3(DIMD/256, RR*BQ), 256>>>(PLN, pool_w, pool_b, QUER,
                                                   DIMD, 0, (long long)DIMD*DIMD, DIMD);

    // ---- Stage E: relevance scores ----
    gemv_rb_kernel<<<dim3(512/256, RR*BQ), 256>>>(QUER, rel_w1, rel_b1, QC,
                                                  512, DIMD, 0LL, 0);
    gemm(retr, rel_w1, nullptr, HBUF,
         RR*BQ*KKC, 512, DIMD, DIMD, 512, 512,
         1, 0,0,0, 1, 0,0,0, 1.0f, 0, 0);
    rel_kernel<<<RR*BQ*KKC, 256>>>(HBUF, QC, rel_w2, rel_b2, REL);

    // ---- Stage F: threshold + top-k + gather ----
    topk_kernel<<<BQ, 256>>>(REL, TI, KV, AV);
    gather_kernel<<<dim3(MAXR, BQ), 256>>>(retr, TI, SEL);

    // ---- Stage G: fusion cross-attention ----
    gemm(x,   in_w,                       in_b,          QP, MS, DIMD, DIMD, DIMD, DIMD, DIMD,
         1, 0,0,0, 1, 0,0,0, 1.0f, 0, 0);
    gemm(SEL, in_w + (size_t)DIMD*DIMD,   in_b + DIMD,   KP, BQ*MAXR, DIMD, DIMD, DIMD, DIMD, DIMD,
         1, 0,0,0, 1, 0,0,0, 1.0f, 0, 0);
    gemm(SEL, in_w + (size_t)2*DIMD*DIMD, in_b + 2*DIMD, VP, BQ*MAXR, DIMD, DIMD, DIMD, DIMD, DIMD,
         1, 0,0,0, 1, 0,0,0, 1.0f, 0, 0);

    // attention scores: [b,h]: (S x HD) @ (MAXR x HD)^T, alpha = 1/sqrt(HD)
    gemm(QP, KP, nullptr, ATT,
         SEQ, MAXR, HDIM, DIMD, DIMD, MAXR,
         BQ*NH, (long long)SEQ*DIMD, (long long)MAXR*DIMD, (long long)NH*SEQ*MAXR,
         NH, HDIM, HDIM, (long long)SEQ*MAXR,
         0.08838834764831845f, 1, 0);

    attn_softmax_kernel<<<dim3(SEQ, NH, BQ), 256>>>(ATT, KV);

    // attention output: [b,h]: (S x MAXR) @ (MAXR x HD) -> AO[b][s][h*HD+:]
    gemm(ATT, VP, nullptr, AO,
         SEQ, HDIM, MAXR, MAXR, DIMD, DIMD,
         BQ*NH, (long long)NH*SEQ*MAXR, (long long)MAXR*DIMD, (long long)SEQ*DIMD,
         NH, (long long)SEQ*MAXR, HDIM, HDIM,
         1.0f, 0, 0);

    // out projection
    gemm(AO, out_w, out_b, FUSED, MS, DIMD, DIMD, DIMD, DIMD, DIMD,
         1, 0,0,0, 1, 0,0,0, 1.0f, 0, 0);

    // residual + LN + per-batch select
    final_kernel<<<MS, 256>>>(x, FUSED, fln_g, fln_b, AV, (float*)d_out);
}

// round 4
// speedup vs baseline: 2.5452x; 2.5452x over previous
#include <cuda_runtime.h>
#include <math.h>

#define DIMD 1024
#define BQ   4
#define SEQ  2048
#define RR   3
#define KKC  256
#define MAXR 256
#define NH   8
#define HDIM 128

// ---------------- scratch (device globals; no allocs allowed) ----------------
constexpr size_t SZ_QF   = (size_t)RR*BQ*SEQ*DIMD;
constexpr size_t SZ_ROW  = (size_t)BQ*SEQ*DIMD;
constexpr size_t SZ_SC   = (size_t)RR*BQ*SEQ*SEQ;
constexpr size_t SZ_ATT  = (size_t)BQ*NH*SEQ*MAXR;
constexpr size_t SZ_HBUF = (size_t)RR*BQ*KKC*512;
constexpr size_t SZ_SEL  = (size_t)BQ*MAXR*DIMD;
constexpr size_t SZ_RBV  = (size_t)RR*BQ*SEQ;

constexpr size_t OFF_QF     = 0;
constexpr size_t OFF_SC     = OFF_QF   + SZ_QF;
constexpr size_t OFF_QP     = OFF_SC   + SZ_SC;
constexpr size_t OFF_AO     = OFF_QP   + SZ_ROW;
constexpr size_t OFF_FUSED  = OFF_AO   + SZ_ROW;
constexpr size_t OFF_ATT    = OFF_FUSED+ SZ_ROW;
constexpr size_t OFF_HBUF   = OFF_ATT  + SZ_ATT;
constexpr size_t OFF_SEL    = OFF_HBUF + SZ_HBUF;
constexpr size_t OFF_KP     = OFF_SEL  + SZ_SEL;
constexpr size_t OFF_VP     = OFF_KP   + SZ_SEL;
constexpr size_t OFF_RINV   = OFF_VP   + SZ_SEL;
constexpr size_t OFF_W      = OFF_RINV + SZ_RBV;
constexpr size_t OFF_POOLED = OFF_W    + SZ_RBV;
constexpr size_t OFF_PLN    = OFF_POOLED + (size_t)RR*BQ*DIMD;
constexpr size_t OFF_QUER   = OFF_PLN    + (size_t)RR*BQ*DIMD;
constexpr size_t OFF_QC     = OFF_QUER   + (size_t)RR*BQ*DIMD;
constexpr size_t OFF_REL    = OFF_QC     + (size_t)RR*BQ*512;
constexpr size_t SCRATCH_TOTAL = OFF_REL + (size_t)RR*BQ*KKC;

__device__ float g_scratch[SCRATCH_TOTAL];
__device__ int   g_topidx[BQ*MAXR];
__device__ int   g_keyvalid[BQ*MAXR];
__device__ int   g_anyvalid[BQ];

// ---------------- helpers ----------------
__device__ __forceinline__ float gelu_f(float v){
    return 0.5f*v*(1.0f + erff(v*0.7071067811865475f));
}

typedef unsigned long long ull;

__device__ __forceinline__ ull pack2(float lo, float hi){
    ull r;
    asm("mov.b64 %0, {%1, %2};" : "=l"(r) : "f"(lo), "f"(hi));
    return r;
}
__device__ __forceinline__ void unpack2(ull v, float& lo, float& hi){
    asm("mov.b64 {%0, %1}, %2;" : "=f"(lo), "=f"(hi) : "l"(v));
}
__device__ __forceinline__ void fma2(ull& d, ull a, ull b){
    asm("fma.rn.f32x2 %0, %1, %2, %0;" : "+l"(d) : "l"(a), "l"(b));
}

__device__ __forceinline__ float bsum(float v){
    __shared__ float sh[32]; __shared__ float total;
    int lane = threadIdx.x & 31, w = threadIdx.x >> 5;
    #pragma unroll
    for (int o=16;o;o>>=1) v += __shfl_down_sync(0xffffffffu, v, o);
    __syncthreads();
    if (lane==0) sh[w] = v;
    __syncthreads();
    if (w==0){
        int nw = blockDim.x >> 5;
        float t = (lane < nw) ? sh[lane] : 0.f;
        #pragma unroll
        for (int o=16;o;o>>=1) t += __shfl_down_sync(0xffffffffu, t, o);
        if (lane==0) total = t;
    }
    __syncthreads();
    return total;
}

__device__ __forceinline__ float bmax(float v){
    __shared__ float sh[32]; __shared__ float total;
    int lane = threadIdx.x & 31, w = threadIdx.x >> 5;
    #pragma unroll
    for (int o=16;o;o>>=1) v = fmaxf(v, __shfl_down_sync(0xffffffffu, v, o));
    __syncthreads();
    if (lane==0) sh[w] = v;
    __syncthreads();
    if (w==0){
        int nw = blockDim.x >> 5;
        float t = (lane < nw) ? sh[lane] : -INFINITY;
        #pragma unroll
        for (int o=16;o;o>>=1) t = fmaxf(t, __shfl_down_sync(0xffffffffu, t, o));
        if (lane==0) total = t;
    }
    __syncthreads();
    return total;
}

// ---------------- batched SGEMM: C = act(alpha*A@B(^T) + bias) ----------------
// 128x128x8 tile, 256 threads, 8x8 microtile via fma.rn.f32x2, double-buffered.
// REQUIRES: M%128==0, N%128==0, K%8==0, leading dims % 4 == 0.
#define TM 128
#define TN 128
#define TK 8
#define LDS_S 132   // padded plane stride (floats); 132*4 divisible by 16

__global__ __launch_bounds__(256, 2)
void gemm_kernel(const float* __restrict__ A, const float* __restrict__ Bm,
                 const float* __restrict__ bias, float* __restrict__ C,
                 int M, int N, int K, int lda, int ldb, int ldc,
                 long long sA1, long long sB1, long long sC1, long long sBias1,
                 int batch2,
                 long long sA2, long long sB2, long long sC2,
                 float alpha, int transB, int act)
{
    int z = blockIdx.z;
    int b1 = z / batch2, b2 = z % batch2;
    A  += b1*sA1 + b2*sA2;
    Bm += b1*sB1 + b2*sB2;
    C  += b1*sC1 + b2*sC2;
    if (bias) bias += b1*sBias1;

    __shared__ __align__(16) float As[2][TK*LDS_S];
    __shared__ __align__(16) float Bs[2][TK*LDS_S];

    int tid = threadIdx.x;
    int tx = tid & 15, ty = tid >> 4;
    int m0 = blockIdx.y * TM, n0 = blockIdx.x * TN;

    int arow = tid >> 1, ak4 = (tid & 1) * 4;
    const float* Aptr = A + (long long)(m0 + arow)*lda + ak4;

    const float* Bptr;
    int brow, bcol;
    if (!transB){ brow = tid >> 5; bcol = (tid & 31) * 4; Bptr = Bm + (long long)brow*ldb + n0 + bcol; }
    else        { brow = tid >> 1; bcol = (tid & 1) * 4;  Bptr = Bm + (long long)(n0 + brow)*ldb + bcol; }

    ull acc[8][4];
    #pragma unroll
    for (int i=0;i<8;i++)
        #pragma unroll
        for (int j=0;j<4;j++) acc[i][j] = 0ULL;

    float4 aR = *reinterpret_cast<const float4*>(Aptr);
    float4 bR = *reinterpret_cast<const float4*>(Bptr);

    {
        float* ap = &As[0][0];
        ap[(ak4+0)*LDS_S + arow] = aR.x;
        ap[(ak4+1)*LDS_S + arow] = aR.y;
        ap[(ak4+2)*LDS_S + arow] = aR.z;
        ap[(ak4+3)*LDS_S + arow] = aR.w;
        float* bp = &Bs[0][0];
        if (!transB){
            *reinterpret_cast<float4*>(&bp[brow*LDS_S + bcol]) = bR;
        } else {
            bp[(bcol+0)*LDS_S + brow] = bR.x;
            bp[(bcol+1)*LDS_S + brow] = bR.y;
            bp[(bcol+2)*LDS_S + brow] = bR.z;
            bp[(bcol+3)*LDS_S + brow] = bR.w;
        }
    }
    __syncthreads();

    int cur = 0;
    for (int k0 = TK; k0 < K; k0 += TK){
        aR = *reinterpret_cast<const float4*>(Aptr + k0);
        if (!transB) bR = *reinterpret_cast<const float4*>(Bptr + (long long)k0*ldb);
        else         bR = *reinterpret_cast<const float4*>(Bptr + k0);

        #pragma unroll
        for (int kk = 0; kk < TK; kk++){
            const float* as = &As[cur][kk*LDS_S];
            const float* bs = &Bs[cur][kk*LDS_S];
            float4 a0 = *reinterpret_cast<const float4*>(as + ty*4);
            float4 a1 = *reinterpret_cast<const float4*>(as + 64 + ty*4);
            ulonglong2 b0 = *reinterpret_cast<const ulonglong2*>(bs + tx*4);
            ulonglong2 b1 = *reinterpret_cast<const ulonglong2*>(bs + 64 + tx*4);
            ull bb[4] = {b0.x, b0.y, b1.x, b1.y};
            float aa[8] = {a0.x,a0.y,a0.z,a0.w, a1.x,a1.y,a1.z,a1.w};
            #pragma unroll
            for (int i=0;i<8;i++){
                ull ad = pack2(aa[i], aa[i]);
                #pragma unroll
                for (int j=0;j<4;j++) fma2(acc[i][j], ad, bb[j]);
            }
        }

        int nxt = cur ^ 1;
        {
            float* ap = &As[nxt][0];
            ap[(ak4+0)*LDS_S + arow] = aR.x;
            ap[(ak4+1)*LDS_S + arow] = aR.y;
            ap[(ak4+2)*LDS_S + arow] = aR.z;
            ap[(ak4+3)*LDS_S + arow] = aR.w;
            float* bp = &Bs[nxt][0];
            if (!transB){
                *reinterpret_cast<float4*>(&bp[brow*LDS_S + bcol]) = bR;
            } else {
                bp[(bcol+0)*LDS_S + brow] = bR.x;
                bp[(bcol+1)*LDS_S + brow] = bR.y;
                bp[(bcol+2)*LDS_S + brow] = bR.z;
                bp[(bcol+3)*LDS_S + brow] = bR.w;
            }
        }
        __syncthreads();
        cur = nxt;
    }

    #pragma unroll
    for (int kk = 0; kk < TK; kk++){
        const float* as = &As[cur][kk*LDS_S];
        const float* bs = &Bs[cur][kk*LDS_S];
        float4 a0 = *reinterpret_cast<const float4*>(as + ty*4);
        float4 a1 = *reinterpret_cast<const float4*>(as + 64 + ty*4);
        ulonglong2 b0 = *reinterpret_cast<const ulonglong2*>(bs + tx*4);
        ulonglong2 b1 = *reinterpret_cast<const ulonglong2*>(bs + 64 + tx*4);
        ull bb[4] = {b0.x, b0.y, b1.x, b1.y};
        float aa[8] = {a0.x,a0.y,a0.z,a0.w, a1.x,a1.y,a1.z,a1.w};
        #pragma unroll
        for (int i=0;i<8;i++){
            ull ad = pack2(aa[i], aa[i]);
            #pragma unroll
            for (int j=0;j<4;j++) fma2(acc[i][j], ad, bb[j]);
        }
    }

    #pragma unroll
    for (int i=0;i<8;i++){
        int gm = m0 + ((i<4) ? (ty*4 + i) : (64 + ty*4 + (i-4)));
        #pragma unroll
        for (int g=0; g<2; g++){
            int gn = n0 + g*64 + tx*4;
            float v0,v1,v2,v3;
            unpack2(acc[i][g*2+0], v0, v1);
            unpack2(acc[i][g*2+1], v2, v3);
            v0 *= alpha; v1 *= alpha; v2 *= alpha; v3 *= alpha;
            if (bias){
                float4 bv = *reinterpret_cast<const float4*>(bias + gn);
                v0 += bv.x; v1 += bv.y; v2 += bv.z; v3 += bv.w;
            }
            if (act == 1){
                v0 = gelu_f(v0); v1 = gelu_f(v1); v2 = gelu_f(v2); v3 = gelu_f(v3);
            }
            float4 o; o.x=v0; o.y=v1; o.z=v2; o.w=v3;
            *reinterpret_cast<float4*>(&C[(long long)gm*ldc + gn]) = o;
        }
    }
}

// ---------------- pooling softmax (in-place exp, store 1/Z) ----------------
__global__ void softmax_rows_kernel(float* __restrict__ sc, float* __restrict__ rinv){
    long long row = blockIdx.x;
    float* p = sc + row*SEQ;
    float m = -INFINITY;
    for (int t=threadIdx.x; t<SEQ; t+=256) m = fmaxf(m, p[t]);
    m = bmax(m);
    float z = 0.f;
    for (int t=threadIdx.x; t<SEQ; t+=256){ float e = __expf(p[t]-m); p[t]=e; z += e; }
    z = bsum(z);
    if (threadIdx.x==0) rinv[row] = 1.0f/z;
}

__global__ void colw_kernel(const float* __restrict__ sc, const float* __restrict__ rinv,
                            float* __restrict__ w){
    int rb = blockIdx.y;
    int t  = blockIdx.x*128 + threadIdx.x;
    const float* p  = sc + (long long)rb*SEQ*SEQ + t;
    const float* ri = rinv + rb*SEQ;
    float acc = 0.f;
    for (int s=0; s<SEQ; s++) acc += p[(long long)s*SEQ] * ri[s];
    w[rb*SEQ + t] = acc * (1.0f/(float)SEQ);
}

__global__ void pooled_kernel(const float* __restrict__ qf, const float* __restrict__ w,
                              float* __restrict__ pooled){
    int rb = blockIdx.y;
    int d  = blockIdx.x*256 + threadIdx.x;
    const float* q  = qf + (long long)rb*SEQ*DIMD + d;
    const float* wp = w + rb*SEQ;
    float acc = 0.f;
    for (int t=0; t<SEQ; t++) acc += wp[t]*q[(long long)t*DIMD];
    pooled[rb*DIMD + d] = acc;
}

__global__ void lnvec_kernel(const float* __restrict__ in, const float* __restrict__ g,
                             const float* __restrict__ b_, float* __restrict__ out){
    int rb = blockIdx.x; int r = rb / BQ;
    const float* p = in + rb*DIMD;
    float s = 0.f;
    for (int i=threadIdx.x;i<DIMD;i+=256) s += p[i];
    float mean = bsum(s)*(1.0f/DIMD);
    float v = 0.f;
    for (int i=threadIdx.x;i<DIMD;i+=256){ float d=p[i]-mean; v += d*d; }
    float var = bsum(v)*(1.0f/DIMD);
    float rs = rsqrtf(var + 1e-5f);
    for (int i=threadIdx.x;i<DIMD;i+=256)
        out[rb*DIMD+i] = (p[i]-mean)*rs*g[r*DIMD+i] + b_[r*DIMD+i];
}

__global__ void gemv_rb_kernel(const float* __restrict__ vin, const float* __restrict__ W,
                               const float* __restrict__ bias, float* __restrict__ out,
                               int N, int Koff, long long wstride, int bstride){
    int rb = blockIdx.y; int r = rb / BQ;
    int e = blockIdx.x*256 + threadIdx.x;
    __shared__ float sv[DIMD];
    for (int i=threadIdx.x;i<DIMD;i+=256) sv[i] = vin[rb*DIMD+i];
    __syncthreads();
    const float* Wp = W + (long long)r*wstride + (long long)Koff*N;
    if (e < N){
        float acc = 0.f;
        for (int d=0; d<DIMD; d++) acc += sv[d]*Wp[(long long)d*N + e];
        out[rb*N + e] = acc + bias[r*bstride + e];
    }
}

__global__ void rel_kernel(const float* __restrict__ hbuf, const float* __restrict__ qc,
                           const float* __restrict__ w2, const float* __restrict__ b2,
                           float* __restrict__ rel){
    int row = blockIdx.x; int rb = row >> 8;
    const float* hp = hbuf + (long long)row*512;
    const float* qp = qc + rb*512;
    float acc = 0.f;
    for (int n=threadIdx.x; n<512; n+=256)
        acc += gelu_f(hp[n] + qp[n]) * w2[n];
    acc = bsum(acc);
    if (threadIdx.x==0) rel[row] = 1.0f/(1.0f + __expf(-(acc + b2[0])));
}

__global__ void topk_kernel(const float* __restrict__ rel, int* __restrict__ topidx,
                            int* __restrict__ keyvalid, int* __restrict__ anyvalid){
    int b = blockIdx.x;
    __shared__ float v[1024];
    __shared__ int   id[1024];
    for (int i=threadIdx.x; i<1024; i+=256){
        if (i < RR*KKC){
            int r = i >> 8, k = i & 255;
            float s = rel[(r*BQ + b)*KKC + k];
            v[i]  = (s >= 0.5f) ? s : -INFINITY;
            id[i] = i;
        } else { v[i] = -INFINITY; id[i] = 1<<20; }
    }
    __syncthreads();
    for (int k=2; k<=1024; k<<=1){
        for (int j=k>>1; j>0; j>>=1){
            for (int i=threadIdx.x; i<1024; i+=256){
                int ixj = i ^ j;
                if (ixj > i){
                    float vi=v[i], vj=v[ixj]; int ii=id[i], ij=id[ixj];
                    bool before = (vi > vj) || (vi == vj && ii < ij);
                    bool dir = ((i & k) == 0);
                    if (before != dir){ v[i]=vj; v[ixj]=vi; id[i]=ij; id[ixj]=ii; }
                }
            }
            __syncthreads();
        }
    }
    for (int j=threadIdx.x; j<MAXR; j+=256){
        topidx[b*MAXR + j]   = id[j];
        keyvalid[b*MAXR + j] = (v[j] >= 0.5f) ? 1 : 0;
    }
    if (threadIdx.x==0) anyvalid[b] = (v[0] >= 0.5f) ? 1 : 0;
}

__global__ void gather_kernel(const float* __restrict__ retrieved, const int* __restrict__ topidx,
                              float* __restrict__ sel){
    int b = blockIdx.y, j = blockIdx.x;
    int c = topidx[b*MAXR + j];
    int r = c >> 8, k = c & 255;
    const float* src = retrieved + (((long long)(r*BQ + b))*KKC + k)*DIMD;
    float* dst = sel + ((long long)(b*MAXR + j))*DIMD;
    for (int d=threadIdx.x; d<DIMD; d+=256) dst[d] = src[d];
}

__global__ void attn_softmax_kernel(float* __restrict__ att, const int* __restrict__ keyvalid){
    int s = blockIdx.x, h = blockIdx.y, b = blockIdx.z;
    float* p = att + ((((long long)b*NH + h)*SEQ) + s)*MAXR;
    int t = threadIdx.x;
    float val = p[t];
    if (!keyvalid[b*MAXR + t]) val = -1e9f;
    float m = bmax(val);
    float e = __expf(val - m);
    float z = bsum(e);
    p[t] = e / z;
}

__global__ void final_kernel(const float* __restrict__ x, const float* __restrict__ fused,
                             const float* __restrict__ g, const float* __restrict__ bb,
                             const int* __restrict__ anyvalid, float* __restrict__ out){
    long long row = blockIdx.x;
    int b = (int)(row >> 11);
    const float* xp = x + row*DIMD;
    const float* fp = fused + row*DIMD;
    float* op = out + row*DIMD;
    bool any = anyvalid[b] != 0;
    float yv[4]; float s = 0.f;
    #pragma unroll
    for (int i=0;i<4;i++){ int idx = threadIdx.x + i*256; yv[i] = xp[idx] + fp[idx]; s += yv[i]; }
    float mean = bsum(s)*(1.0f/DIMD);
    float v = 0.f;
    #pragma unroll
    for (int i=0;i<4;i++){ float d = yv[i]-mean; v += d*d; }
    float var = bsum(v)*(1.0f/DIMD);
    float rs = rsqrtf(var + 1e-5f);
    #pragma unroll
    for (int i=0;i<4;i++){
        int idx = threadIdx.x + i*256;
        op[idx] = any ? ((yv[i]-mean)*rs*g[idx] + bb[idx]) : xp[idx];
    }
}

// ---------------- host ----------------
static void gemm(const float* A, const float* B, const float* bias, float* C,
                 int M, int N, int K, int lda, int ldb, int ldc,
                 int nb, long long sA1, long long sB1, long long sC1, long long sBias1,
                 int b2, long long sA2, long long sB2, long long sC2,
                 float alpha, int transB, int act)
{
    dim3 grid((N+TN-1)/TN, (M+TM-1)/TM, nb);
    gemm_kernel<<<grid, 256>>>(A,B,bias,C,M,N,K,lda,ldb,ldc,
                               sA1,sB1,sC1,sBias1,b2,sA2,sB2,sC2,alpha,transB,act);
}

extern "C" void kernel_launch(void* const* d_in, const int* in_sizes, int n_in,
                              void* d_out, int out_size)
{
    const float* x       = (const float*)d_in[0];
    const float* retr    = (const float*)d_in[1];
    const float* qg_w1   = (const float*)d_in[2];
    const float* qg_b1   = (const float*)d_in[3];
    const float* qg_w2   = (const float*)d_in[4];
    const float* qg_b2   = (const float*)d_in[5];
    const float* pln_g   = (const float*)d_in[6];
    const float* pln_b   = (const float*)d_in[7];
    const float* pool_w  = (const float*)d_in[8];
    const float* pool_b  = (const float*)d_in[9];
    const float* rel_w1  = (const float*)d_in[10];
    const float* rel_b1  = (const float*)d_in[11];
    const float* rel_w2  = (const float*)d_in[12];
    const float* rel_b2  = (const float*)d_in[13];
    const float* in_w    = (const float*)d_in[14];
    const float* in_b    = (const float*)d_in[15];
    const float* out_w   = (const float*)d_in[16];
    const float* out_b   = (const float*)d_in[17];
    const float* fln_g   = (const float*)d_in[18];
    const float* fln_b   = (const float*)d_in[19];

    float* S = nullptr;
    cudaGetSymbolAddress((void**)&S, g_scratch);
    int *TI=nullptr, *KV=nullptr, *AV=nullptr;
    cudaGetSymbolAddress((void**)&TI, g_topidx);
    cudaGetSymbolAddress((void**)&KV, g_keyvalid);
    cudaGetSymbolAddress((void**)&AV, g_anyvalid);

    float* QF     = S + OFF_QF;
    float* SC     = S + OFF_SC;
    float* QP     = S + OFF_QP;
    float* AO     = S + OFF_AO;
    float* FUSED  = S + OFF_FUSED;
    float* ATT    = S + OFF_ATT;
    float* HBUF   = S + OFF_HBUF;
    float* SEL    = S + OFF_SEL;
    float* KP     = S + OFF_KP;
    float* VP     = S + OFF_VP;
    float* RINV   = S + OFF_RINV;
    float* WCOL   = S + OFF_W;
    float* POOLED = S + OFF_POOLED;
    float* PLN    = S + OFF_PLN;
    float* QUER   = S + OFF_QUER;
    float* QC     = S + OFF_QC;
    float* REL    = S + OFF_REL;

    const int MS = BQ*SEQ;  // 8192

    // ---- Stage A: query-gen MLPs, batched over R (SC reused as hidden buffer) ----
    gemm(x, qg_w1, qg_b1, SC,
         MS, DIMD, DIMD, DIMD, DIMD, DIMD,
         RR, 0, (long long)DIMD*DIMD, (long long)MS*DIMD, DIMD,
         1, 0,0,0, 1.0f, 0, 1);
    gemm(SC, qg_w2, qg_b2, QF,
         MS, DIMD, DIMD, DIMD, DIMD, DIMD,
         RR, (long long)MS*DIMD, (long long)DIMD*DIMD, (long long)MS*DIMD, DIMD,
         1, 0,0,0, 1.0f, 0, 0);

    // ---- Stage B: pooling attention scores = qf @ qf^T / 32 ----
    gemm(QF, QF, nullptr, SC,
         SEQ, SEQ, DIMD, DIMD, DIMD, SEQ,
         RR*BQ, (long long)SEQ*DIMD, (long long)SEQ*DIMD, (long long)SEQ*SEQ, 0,
         1, 0,0,0, 1.0f/32.0f, 1, 0);

    // ---- Stage C: row softmax (in place) + column weights ----
    softmax_rows_kernel<<<RR*BQ*SEQ, 256>>>(SC, RINV);
    colw_kernel<<<dim3(SEQ/128, RR*BQ), 128>>>(SC, RINV, WCOL);

    // ---- Stage D: pooled -> LN -> queries ----
    pooled_kernel<<<dim3(DIMD/256, RR*BQ), 256>>>(QF, WCOL, POOLED);
    lnvec_kernel<<<RR*BQ, 256>>>(POOLED, pln_g, pln_b, PLN);
    gemv_rb_kernel<<<dim3(DIMD/256, RR*BQ), 256>>>(PLN, pool_w, pool_b, QUER,
                                                   DIMD, 0, (long long)DIMD*DIMD, DIMD);

    // ---- Stage E: relevance scores ----
    gemv_rb_kernel<<<dim3(512/256, RR*BQ), 256>>>(QUER, rel_w1, rel_b1, QC,
                                                  512, DIMD, 0LL, 0);
    gemm(retr, rel_w1, nullptr, HBUF,
         RR*BQ*KKC, 512, DIMD, DIMD, 512, 512,
         1, 0,0,0, 0, 1, 0,0,0, 1.0f, 0, 0);
    rel_kernel<<<RR*BQ*KKC, 256>>>(HBUF, QC, rel_w2, rel_b2, REL);

    // ---- Stage F: threshold + top-k + gather ----
    topk_kernel<<<BQ, 256>>>(REL, TI, KV, AV);
    gather_kernel<<<dim3(MAXR, BQ), 256>>>(retr, TI, SEL);

    // ---- Stage G: fusion cross-attention ----
    gemm(x,   in_w,                       in_b,          QP, MS, DIMD, DIMD, DIMD, DIMD, DIMD,
         1, 0,0,0, 0, 1, 0,0,0, 1.0f, 0, 0);
    gemm(SEL, in_w + (size_t)DIMD*DIMD,   in_b + DIMD,   KP, BQ*MAXR, DIMD, DIMD, DIMD, DIMD, DIMD,
         1, 0,0,0, 0, 1, 0,0,0, 1.0f, 0, 0);
    gemm(SEL, in_w + (size_t)2*DIMD*DIMD, in_b + 2*DIMD, VP, BQ*MAXR, DIMD, DIMD, DIMD, DIMD, DIMD,
         1, 0,0,0, 0, 1, 0,0,0, 1.0f, 0, 0);

    gemm(QP, KP, nullptr, ATT,
         SEQ, MAXR, HDIM, DIMD, DIMD, MAXR,
         BQ*NH, (long long)SEQ*DIMD, (long long)MAXR*DIMD, (long long)NH*SEQ*MAXR, 0,
         NH, HDIM, HDIM, (long long)SEQ*MAXR,
         0.08838834764831845f, 1, 0);

    attn_softmax_kernel<<<dim3(SEQ, NH, BQ), 256>>>(ATT, KV);

    gemm(ATT, VP, nullptr, AO,
         SEQ, HDIM, MAXR, MAXR, DIMD, DIMD,
         BQ*NH, (long long)NH*SEQ*MAXR, (long long)MAXR*DIMD, (long long)SEQ*DIMD, 0,
         NH, (long long)SEQ*MAXR, HDIM, HDIM,
         1.0f, 0, 0);

    gemm(AO, out_w, out_b, FUSED, MS, DIMD, DIMD, DIMD, DIMD, DIMD,
         1, 0,0,0, 0, 1, 0,0,0, 1.0f, 0, 0);

    final_kernel<<<MS, 256>>>(x, FUSED, fln_g, fln_b, AV, (float*)d_out);
}

// round 6
// speedup vs baseline: 3.4776x; 1.3663x over previous
#include <cuda_runtime.h>
#include <cuda_bf16.h>
#include <math.h>
#include <stdint.h>

#define DIMD 1024
#define BQ   4
#define SEQ  2048
#define RR   3
#define KKC  256
#define MAXR 256
#define NH   8
#define HDIM 128

// ---------------- fp32 scratch (device globals; no allocs allowed) ----------------
constexpr size_t SZ_QF   = (size_t)RR*BQ*SEQ*DIMD;
constexpr size_t SZ_ROW  = (size_t)BQ*SEQ*DIMD;
constexpr size_t SZ_SC   = (size_t)RR*BQ*SEQ*SEQ;
constexpr size_t SZ_ATT  = (size_t)BQ*NH*SEQ*MAXR;
constexpr size_t SZ_HBUF = (size_t)RR*BQ*KKC*512;
constexpr size_t SZ_SEL  = (size_t)BQ*MAXR*DIMD;
constexpr size_t SZ_RBV  = (size_t)RR*BQ*SEQ;

constexpr size_t OFF_QF     = 0;
constexpr size_t OFF_SC     = OFF_QF   + SZ_QF;
constexpr size_t OFF_QP     = OFF_SC   + SZ_SC;
constexpr size_t OFF_AO     = OFF_QP   + SZ_ROW;
constexpr size_t OFF_FUSED  = OFF_AO   + SZ_ROW;
constexpr size_t OFF_ATT    = OFF_FUSED+ SZ_ROW;
constexpr size_t OFF_HBUF   = OFF_ATT  + SZ_ATT;
constexpr size_t OFF_SEL    = OFF_HBUF + SZ_HBUF;
constexpr size_t OFF_KP     = OFF_SEL  + SZ_SEL;
constexpr size_t OFF_VP     = OFF_KP   + SZ_SEL;
constexpr size_t OFF_RINV   = OFF_VP   + SZ_SEL;
constexpr size_t OFF_W      = OFF_RINV + SZ_RBV;
constexpr size_t OFF_POOLED = OFF_W    + SZ_RBV;
constexpr size_t OFF_PLN    = OFF_POOLED + (size_t)RR*BQ*DIMD;
constexpr size_t OFF_QUER   = OFF_PLN    + (size_t)RR*BQ*DIMD;
constexpr size_t OFF_QC     = OFF_QUER   + (size_t)RR*BQ*DIMD;
constexpr size_t OFF_REL    = OFF_QC     + (size_t)RR*BQ*512;
constexpr size_t SCRATCH_TOTAL = OFF_REL + (size_t)RR*BQ*KKC;

__device__ float g_scratch[SCRATCH_TOTAL];
__device__ int   g_topidx[BQ*MAXR];
__device__ int   g_keyvalid[BQ*MAXR];
__device__ int   g_anyvalid[BQ];

// ---------------- bf16 split scratch ----------------
__device__ __align__(16) __nv_bfloat16 g_xh[(size_t)BQ*SEQ*DIMD];
__device__ __align__(16) __nv_bfloat16 g_xl[(size_t)BQ*SEQ*DIMD];
__device__ __align__(16) __nv_bfloat16 g_w1th[(size_t)RR*DIMD*DIMD];
__device__ __align__(16) __nv_bfloat16 g_w1tl[(size_t)RR*DIMD*DIMD];
__device__ __align__(16) __nv_bfloat16 g_w2th[(size_t)RR*DIMD*DIMD];
__device__ __align__(16) __nv_bfloat16 g_w2tl[(size_t)RR*DIMD*DIMD];
__device__ __align__(16) __nv_bfloat16 g_inw0th[(size_t)DIMD*DIMD];
__device__ __align__(16) __nv_bfloat16 g_inw0tl[(size_t)DIMD*DIMD];
__device__ __align__(16) __nv_bfloat16 g_outwth[(size_t)DIMD*DIMD];
__device__ __align__(16) __nv_bfloat16 g_outwtl[(size_t)DIMD*DIMD];
__device__ __align__(16) __nv_bfloat16 g_Hh[(size_t)RR*BQ*SEQ*DIMD];
__device__ __align__(16) __nv_bfloat16 g_Hl[(size_t)RR*BQ*SEQ*DIMD];
__device__ __align__(16) __nv_bfloat16 g_QFh[(size_t)RR*BQ*SEQ*DIMD];
__device__ __align__(16) __nv_bfloat16 g_QFl[(size_t)RR*BQ*SEQ*DIMD];
__device__ __align__(16) __nv_bfloat16 g_AOh[(size_t)BQ*SEQ*DIMD];
__device__ __align__(16) __nv_bfloat16 g_AOl[(size_t)BQ*SEQ*DIMD];

// ---------------- helpers ----------------
__device__ __forceinline__ uint32_t smem_to_u32(const void* p) {
    uint32_t a;
    asm("{ .reg .u64 t; cvta.to.shared.u64 t, %1; cvt.u32.u64 %0, t; }" : "=r"(a) : "l"(p));
    return a;
}

__device__ __forceinline__ float gelu_f(float v){
    return 0.5f*v*(1.0f + erff(v*0.7071067811865475f));
}

typedef unsigned long long ull;

__device__ __forceinline__ ull pack2(float lo, float hi){
    ull r; asm("mov.b64 %0, {%1, %2};" : "=l"(r) : "f"(lo), "f"(hi)); return r;
}
__device__ __forceinline__ void unpack2(ull v, float& lo, float& hi){
    asm("mov.b64 {%0, %1}, %2;" : "=f"(lo), "=f"(hi) : "l"(v));
}
__device__ __forceinline__ void fma2(ull& d, ull a, ull b){
    asm("fma.rn.f32x2 %0, %1, %2, %0;" : "+l"(d) : "l"(a), "l"(b));
}

__device__ __forceinline__ void ldsm4(uint32_t* r, uint32_t addr){
    asm volatile("ldmatrix.sync.aligned.m8n8.x4.shared.b16 {%0,%1,%2,%3}, [%4];"
        : "=r"(r[0]), "=r"(r[1]), "=r"(r[2]), "=r"(r[3]) : "r"(addr));
}
__device__ __forceinline__ void mma16816(float* d, const uint32_t* a, const uint32_t* b){
    asm volatile("mma.sync.aligned.m16n8k16.row.col.f32.bf16.bf16.f32 "
        "{%0,%1,%2,%3}, {%4,%5,%6,%7}, {%8,%9}, {%0,%1,%2,%3};"
        : "+f"(d[0]), "+f"(d[1]), "+f"(d[2]), "+f"(d[3])
        : "r"(a[0]), "r"(a[1]), "r"(a[2]), "r"(a[3]), "r"(b[0]), "r"(b[1]));
}

__device__ __forceinline__ float bsum(float v){
    __shared__ float sh[32]; __shared__ float total;
    int lane = threadIdx.x & 31, w = threadIdx.x >> 5;
    #pragma unroll
    for (int o=16;o;o>>=1) v += __shfl_down_sync(0xffffffffu, v, o);
    __syncthreads();
    if (lane==0) sh[w] = v;
    __syncthreads();
    if (w==0){
        int nw = blockDim.x >> 5;
        float t = (lane < nw) ? sh[lane] : 0.f;
        #pragma unroll
        for (int o=16;o;o>>=1) t += __shfl_down_sync(0xffffffffu, t, o);
        if (lane==0) total = t;
    }
    __syncthreads();
    return total;
}

__device__ __forceinline__ float bmax(float v){
    __shared__ float sh[32]; __shared__ float total;
    int lane = threadIdx.x & 31, w = threadIdx.x >> 5;
    #pragma unroll
    for (int o=16;o;o>>=1) v = fmaxf(v, __shfl_down_sync(0xffffffffu, v, o));
    __syncthreads();
    if (lane==0) sh[w] = v;
    __syncthreads();
    if (w==0){
        int nw = blockDim.x >> 5;
        float t = (lane < nw) ? sh[lane] : -INFINITY;
        #pragma unroll
        for (int o=16;o;o>>=1) t = fmaxf(t, __shfl_down_sync(0xffffffffu, t, o));
        if (lane==0) total = t;
    }
    __syncthreads();
    return total;
}

// =====================================================================
// HMMA split-bf16 GEMM: C = act(alpha * A@B^T + bias)
// A: [M,K] (Ah,Al) bf16 K-major; B: [N,K] (Bh,Bl) bf16 K-major.
// Ah@Bh + Ah@Bl + Al@Bh with fp32 accumulation via mma.m16n8k16.
// 128x128 tile, 8 warps (warp tile 32x64), K-chunk 32.
// REQUIRES: M%128==0, N%128==0, K%32==0, lda/ldb multiples of 8.
// =====================================================================
__global__ __launch_bounds__(256, 1)
void hgemm_kernel(const __nv_bfloat16* __restrict__ Ah, const __nv_bfloat16* __restrict__ Al,
                  const __nv_bfloat16* __restrict__ Bh, const __nv_bfloat16* __restrict__ Bl,
                  const float* __restrict__ bias, float* __restrict__ Cf,
                  __nv_bfloat16* __restrict__ Chi, __nv_bfloat16* __restrict__ Clo,
                  int M, int N, int K, int lda, int ldb, int ldc,
                  long long sA, long long sB, long long sC, long long sBias,
                  float alpha, int act)
{
    __shared__ __align__(16) uint8_t sm[32768];
    const uint32_t sbase = smem_to_u32(sm);
    const int tid = threadIdx.x, lane = tid & 31, wid = tid >> 5;

    int z = blockIdx.z;
    Ah += z*sA; Al += z*sA; Bh += z*sB; Bl += z*sB;
    if (Cf)  Cf  += z*sC;
    if (Chi){ Chi += z*sC; Clo += z*sC; }
    if (bias) bias += z*sBias;
    const int m0 = blockIdx.y*128, n0 = blockIdx.x*128;

    const int SA_H = 0, SA_L = 8192, SB_H = 16384, SB_L = 24576;

    float acc[2][8][4];
    #pragma unroll
    for (int i=0;i<2;i++)
        #pragma unroll
        for (int j=0;j<8;j++)
            #pragma unroll
            for (int q=0;q<4;q++) acc[i][j][q] = 0.f;

    const int lrow = tid >> 2;      // 0..63
    const int lq   = tid & 3;       // 16B column within 64B row
    const int m_off = (wid >> 1) * 32;
    const int n_off = (wid & 1) * 64;

    for (int c = 0; c < K; c += 32){
        __syncthreads();
        #pragma unroll
        for (int p = 0; p < 2; p++){
            int row = p*64 + lrow;
            size_t ga = (size_t)(m0+row)*lda + c + lq*8;
            size_t gb = (size_t)(n0+row)*ldb + c + lq*8;
            uint32_t so = (uint32_t)row*64 + ((uint32_t)(lq ^ ((row>>1)&3)) << 4);
            *reinterpret_cast<uint4*>(sm + SA_H + so) = *reinterpret_cast<const uint4*>(Ah + ga);
            *reinterpret_cast<uint4*>(sm + SA_L + so) = *reinterpret_cast<const uint4*>(Al + ga);
            *reinterpret_cast<uint4*>(sm + SB_H + so) = *reinterpret_cast<const uint4*>(Bh + gb);
            *reinterpret_cast<uint4*>(sm + SB_L + so) = *reinterpret_cast<const uint4*>(Bl + gb);
        }
        __syncthreads();

        #pragma unroll
        for (int kk = 0; kk < 32; kk += 16){
            uint32_t ah[2][4], al2[2][4], bh[8][2], bl2[8][2];
            #pragma unroll
            for (int mi = 0; mi < 2; mi++){
                int row = m_off + mi*16 + (lane & 15);
                int cu  = (kk >> 3) + (lane >> 4);
                uint32_t ad = sbase + SA_H + row*64 + ((uint32_t)(cu ^ ((row>>1)&3)) << 4);
                ldsm4(ah[mi],  ad);
                ldsm4(al2[mi], ad + (SA_L - SA_H));
            }
            #pragma unroll
            for (int g = 0; g < 4; g++){
                int row = n_off + g*16 + (lane & 7) + ((lane >> 4) << 3);
                int cu  = (kk >> 3) + ((lane >> 3) & 1);
                uint32_t bd = sbase + SB_H + row*64 + ((uint32_t)(cu ^ ((row>>1)&3)) << 4);
                uint32_t t[4];
                ldsm4(t, bd);
                bh[2*g][0]=t[0]; bh[2*g][1]=t[1]; bh[2*g+1][0]=t[2]; bh[2*g+1][1]=t[3];
                ldsm4(t, bd + (SB_L - SB_H));
                bl2[2*g][0]=t[0]; bl2[2*g][1]=t[1]; bl2[2*g+1][0]=t[2]; bl2[2*g+1][1]=t[3];
            }
            #pragma unroll
            for (int mi = 0; mi < 2; mi++)
                #pragma unroll
                for (int nb = 0; nb < 8; nb++){
                    mma16816(acc[mi][nb], ah[mi],  bh[nb]);
                    mma16816(acc[mi][nb], ah[mi],  bl2[nb]);
                    mma16816(acc[mi][nb], al2[mi], bh[nb]);
                }
        }
    }

    // epilogue: d0,d1 -> (row = lane/4, col = (lane%4)*2 +0/1); d2,d3 -> row+8
    const int r0w = lane >> 2, cqw = (lane & 3) * 2;
    #pragma unroll
    for (int mi = 0; mi < 2; mi++){
        #pragma unroll
        for (int nb = 0; nb < 8; nb++){
            int col = n0 + n_off + nb*8 + cqw;
            float b0 = 0.f, b1 = 0.f;
            if (bias){ b0 = bias[col]; b1 = bias[col+1]; }
            #pragma unroll
            for (int h = 0; h < 2; h++){
                int rr = m0 + m_off + mi*16 + r0w + h*8;
                float v0 = acc[mi][nb][h*2+0]*alpha + b0;
                float v1 = acc[mi][nb][h*2+1]*alpha + b1;
                if (act == 1){ v0 = gelu_f(v0); v1 = gelu_f(v1); }
                size_t o = (size_t)rr*ldc + col;
                if (Cf){ Cf[o] = v0; Cf[o+1] = v1; }
                if (Chi){
                    __nv_bfloat16 h0 = __float2bfloat16(v0), h1 = __float2bfloat16(v1);
                    Chi[o]   = h0; Chi[o+1] = h1;
                    Clo[o]   = __float2bfloat16(v0 - __bfloat162float(h0));
                    Clo[o+1] = __float2bfloat16(v1 - __bfloat162float(h1));
                }
            }
        }
    }
}

// ---------------- fp32 -> bf16 hi/lo split ----------------
__global__ void split_kernel(const float* __restrict__ src, __nv_bfloat16* __restrict__ h,
                             __nv_bfloat16* __restrict__ l, int n){
    int i = blockIdx.x*256 + threadIdx.x;
    if (i < n){
        float v = src[i];
        __nv_bfloat16 a = __float2bfloat16(v);
        h[i] = a;
        l[i] = __float2bfloat16(v - __bfloat162float(a));
    }
}

// transpose + split: W [z][rows][cols] -> T[z][cols][rows] (hi/lo). rows,cols % 32 == 0.
__global__ void tsplit_kernel(const float* __restrict__ W, __nv_bfloat16* __restrict__ Th,
                              __nv_bfloat16* __restrict__ Tl, int rows, int cols){
    __shared__ float t[32][33];
    int z = blockIdx.z;
    W  += (size_t)z*rows*cols;
    Th += (size_t)z*rows*cols;
    Tl += (size_t)z*rows*cols;
    int r0 = blockIdx.y*32, c0 = blockIdx.x*32;
    int tx = threadIdx.x, ty = threadIdx.y;  // 32 x 8
    #pragma unroll
    for (int i = 0; i < 32; i += 8)
        t[ty+i][tx] = W[(size_t)(r0+ty+i)*cols + c0+tx];
    __syncthreads();
    #pragma unroll
    for (int i = 0; i < 32; i += 8){
        float v = t[tx][ty+i];
        size_t o = (size_t)(c0+ty+i)*rows + r0+tx;
        __nv_bfloat16 h = __float2bfloat16(v);
        Th[o] = h;
        Tl[o] = __float2bfloat16(v - __bfloat162float(h));
    }
}

// ---------------- f32x2 batched SGEMM (small-GEMM path, from R4) ----------------
#define TM 128
#define TN 128
#define TK 8
#define LDS_S 132

__global__ __launch_bounds__(256, 2)
void gemm_kernel(const float* __restrict__ A, const float* __restrict__ Bm,
                 const float* __restrict__ bias, float* __restrict__ C,
                 int M, int N, int K, int lda, int ldb, int ldc,
                 long long sA1, long long sB1, long long sC1, long long sBias1,
                 int batch2,
                 long long sA2, long long sB2, long long sC2,
                 float alpha, int transB, int act)
{
    int z = blockIdx.z;
    int b1 = z / batch2, b2 = z % batch2;
    A  += b1*sA1 + b2*sA2;
    Bm += b1*sB1 + b2*sB2;
    C  += b1*sC1 + b2*sC2;
    if (bias) bias += b1*sBias1;

    __shared__ __align__(16) float As[2][TK*LDS_S];
    __shared__ __align__(16) float Bs[2][TK*LDS_S];

    int tid = threadIdx.x;
    int tx = tid & 15, ty = tid >> 4;
    int m0 = blockIdx.y * TM, n0 = blockIdx.x * TN;

    int arow = tid >> 1, ak4 = (tid & 1) * 4;
    const float* Aptr = A + (long long)(m0 + arow)*lda + ak4;

    const float* Bptr;
    int brow, bcol;
    if (!transB){ brow = tid >> 5; bcol = (tid & 31) * 4; Bptr = Bm + (long long)brow*ldb + n0 + bcol; }
    else        { brow = tid >> 1; bcol = (tid & 1) * 4;  Bptr = Bm + (long long)(n0 + brow)*ldb + bcol; }

    ull acc[8][4];
    #pragma unroll
    for (int i=0;i<8;i++)
        #pragma unroll
        for (int j=0;j<4;j++) acc[i][j] = 0ULL;

    float4 aR = *reinterpret_cast<const float4*>(Aptr);
    float4 bR = *reinterpret_cast<const float4*>(Bptr);

    {
        float* ap = &As[0][0];
        ap[(ak4+0)*LDS_S + arow] = aR.x;
        ap[(ak4+1)*LDS_S + arow] = aR.y;
        ap[(ak4+2)*LDS_S + arow] = aR.z;
        ap[(ak4+3)*LDS_S + arow] = aR.w;
        float* bp = &Bs[0][0];
        if (!transB){
            *reinterpret_cast<float4*>(&bp[brow*LDS_S + bcol]) = bR;
        } else {
            bp[(bcol+0)*LDS_S + brow] = bR.x;
            bp[(bcol+1)*LDS_S + brow] = bR.y;
            bp[(bcol+2)*LDS_S + brow] = bR.z;
            bp[(bcol+3)*LDS_S + brow] = bR.w;
        }
    }
    __syncthreads();

    int cur = 0;
    for (int k0 = TK; k0 < K; k0 += TK){
        aR = *reinterpret_cast<const float4*>(Aptr + k0);
        if (!transB) bR = *reinterpret_cast<const float4*>(Bptr + (long long)k0*ldb);
        else         bR = *reinterpret_cast<const float4*>(Bptr + k0);

        #pragma unroll
        for (int kk = 0; kk < TK; kk++){
            const float* as = &As[cur][kk*LDS_S];
            const float* bs = &Bs[cur][kk*LDS_S];
            float4 a0 = *reinterpret_cast<const float4*>(as + ty*4);
            float4 a1 = *reinterpret_cast<const float4*>(as + 64 + ty*4);
            ulonglong2 b0 = *reinterpret_cast<const ulonglong2*>(bs + tx*4);
            ulonglong2 b1 = *reinterpret_cast<const ulonglong2*>(bs + 64 + tx*4);
            ull bb[4] = {b0.x, b0.y, b1.x, b1.y};
            float aa[8] = {a0.x,a0.y,a0.z,a0.w, a1.x,a1.y,a1.z,a1.w};
            #pragma unroll
            for (int i=0;i<8;i++){
                ull ad = pack2(aa[i], aa[i]);
                #pragma unroll
                for (int j=0;j<4;j++) fma2(acc[i][j], ad, bb[j]);
            }
        }

        int nxt = cur ^ 1;
        {
            float* ap = &As[nxt][0];
            ap[(ak4+0)*LDS_S + arow] = aR.x;
            ap[(ak4+1)*LDS_S + arow] = aR.y;
            ap[(ak4+2)*LDS_S + arow] = aR.z;
            ap[(ak4+3)*LDS_S + arow] = aR.w;
            float* bp = &Bs[nxt][0];
            if (!transB){
                *reinterpret_cast<float4*>(&bp[brow*LDS_S + bcol]) = bR;
            } else {
                bp[(bcol+0)*LDS_S + brow] = bR.x;
                bp[(bcol+1)*LDS_S + brow] = bR.y;
                bp[(bcol+2)*LDS_S + brow] = bR.z;
                bp[(bcol+3)*LDS_S + brow] = bR.w;
            }
        }
        __syncthreads();
        cur = nxt;
    }

    #pragma unroll
    for (int kk = 0; kk < TK; kk++){
        const float* as = &As[cur][kk*LDS_S];
        const float* bs = &Bs[cur][kk*LDS_S];
        float4 a0 = *reinterpret_cast<const float4*>(as + ty*4);
        float4 a1 = *reinterpret_cast<const float4*>(as + 64 + ty*4);
        ulonglong2 b0 = *reinterpret_cast<const ulonglong2*>(bs + tx*4);
        ulonglong2 b1 = *reinterpret_cast<const ulonglong2*>(bs + 64 + tx*4);
        ull bb[4] = {b0.x, b0.y, b1.x, b1.y};
        float aa[8] = {a0.x,a0.y,a0.z,a0.w, a1.x,a1.y,a1.z,a1.w};
        #pragma unroll
        for (int i=0;i<8;i++){
            ull ad = pack2(aa[i], aa[i]);
            #pragma unroll
            for (int j=0;j<4;j++) fma2(acc[i][j], ad, bb[j]);
        }
    }

    #pragma unroll
    for (int i=0;i<8;i++){
        int gm = m0 + ((i<4) ? (ty*4 + i) : (64 + ty*4 + (i-4)));
        #pragma unroll
        for (int g=0; g<2; g++){
            int gn = n0 + g*64 + tx*4;
            float v0,v1,v2,v3;
            unpack2(acc[i][g*2+0], v0, v1);
            unpack2(acc[i][g*2+1], v2, v3);
            v0 *= alpha; v1 *= alpha; v2 *= alpha; v3 *= alpha;
            if (bias){
                float4 bv = *reinterpret_cast<const float4*>(bias + gn);
                v0 += bv.x; v1 += bv.y; v2 += bv.z; v3 += bv.w;
            }
            if (act == 1){
                v0 = gelu_f(v0); v1 = gelu_f(v1); v2 = gelu_f(v2); v3 = gelu_f(v3);
            }
            float4 o; o.x=v0; o.y=v1; o.z=v2; o.w=v3;
            *reinterpret_cast<float4*>(&C[(long long)gm*ldc + gn]) = o;
        }
    }
}

// ---------------- non-GEMM kernels ----------------
__global__ void softmax_rows_kernel(float* __restrict__ sc, float* __restrict__ rinv){
    long long row = blockIdx.x;
    float* p = sc + row*SEQ;
    float m = -INFINITY;
    for (int t=threadIdx.x; t<SEQ; t+=256) m = fmaxf(m, p[t]);
    m = bmax(m);
    float z = 0.f;
    for (int t=threadIdx.x; t<SEQ; t+=256){ float e = __expf(p[t]-m); p[t]=e; z += e; }
    z = bsum(z);
    if (threadIdx.x==0) rinv[row] = 1.0f/z;
}

__global__ void colw_kernel(const float* __restrict__ sc, const float* __restrict__ rinv,
                            float* __restrict__ w){
    int rb = blockIdx.y;
    int t  = blockIdx.x*128 + threadIdx.x;
    const float* p  = sc + (long long)rb*SEQ*SEQ + t;
    const float* ri = rinv + rb*SEQ;
    float acc = 0.f;
    for (int s=0; s<SEQ; s++) acc += p[(long long)s*SEQ] * ri[s];
    w[rb*SEQ + t] = acc * (1.0f/(float)SEQ);
}

__global__ void pooled_kernel(const float* __restrict__ qf, const float* __restrict__ w,
                              float* __restrict__ pooled){
    int rb = blockIdx.y;
    int d  = blockIdx.x*256 + threadIdx.x;
    const float* q  = qf + (long long)rb*SEQ*DIMD + d;
    const float* wp = w + rb*SEQ;
    float acc = 0.f;
    for (int t=0; t<SEQ; t++) acc += wp[t]*q[(long long)t*DIMD];
    pooled[rb*DIMD + d] = acc;
}

__global__ void lnvec_kernel(const float* __restrict__ in, const float* __restrict__ g,
                             const float* __restrict__ b_, float* __restrict__ out){
    int rb = blockIdx.x; int r = rb / BQ;
    const float* p = in + rb*DIMD;
    float s = 0.f;
    for (int i=threadIdx.x;i<DIMD;i+=256) s += p[i];
    float mean = bsum(s)*(1.0f/DIMD);
    float v = 0.f;
    for (int i=threadIdx.x;i<DIMD;i+=256){ float d=p[i]-mean; v += d*d; }
    float var = bsum(v)*(1.0f/DIMD);
    float rs = rsqrtf(var + 1e-5f);
    for (int i=threadIdx.x;i<DIMD;i+=256)
        out[rb*DIMD+i] = (p[i]-mean)*rs*g[r*DIMD+i] + b_[r*DIMD+i];
}

__global__ void gemv_rb_kernel(const float* __restrict__ vin, const float* __restrict__ W,
                               const float* __restrict__ bias, float* __restrict__ out,
                               int N, int Koff, long long wstride, int bstride){
    int rb = blockIdx.y; int r = rb / BQ;
    int e = blockIdx.x*256 + threadIdx.x;
    __shared__ float sv[DIMD];
    for (int i=threadIdx.x;i<DIMD;i+=256) sv[i] = vin[rb*DIMD+i];
    __syncthreads();
    const float* Wp = W + (long long)r*wstride + (long long)Koff*N;
    if (e < N){
        float acc = 0.f;
        for (int d=0; d<DIMD; d++) acc += sv[d]*Wp[(long long)d*N + e];
        out[rb*N + e] = acc + bias[r*bstride + e];
    }
}

__global__ void rel_kernel(const float* __restrict__ hbuf, const float* __restrict__ qc,
                           const float* __restrict__ w2, const float* __restrict__ b2,
                           float* __restrict__ rel){
    int row = blockIdx.x; int rb = row >> 8;
    const float* hp = hbuf + (long long)row*512;
    const float* qp = qc + rb*512;
    float acc = 0.f;
    for (int n=threadIdx.x; n<512; n+=256)
        acc += gelu_f(hp[n] + qp[n]) * w2[n];
    acc = bsum(acc);
    if (threadIdx.x==0) rel[row] = 1.0f/(1.0f + __expf(-(acc + b2[0])));
}

__global__ void topk_kernel(const float* __restrict__ rel, int* __restrict__ topidx,
                            int* __restrict__ keyvalid, int* __restrict__ anyvalid){
    int b = blockIdx.x;
    __shared__ float v[1024];
    __shared__ int   id[1024];
    for (int i=threadIdx.x; i<1024; i+=256){
        if (i < RR*KKC){
            int r = i >> 8, k = i & 255;
            float s = rel[(r*BQ + b)*KKC + k];
            v[i]  = (s >= 0.5f) ? s : -INFINITY;
            id[i] = i;
        } else { v[i] = -INFINITY; id[i] = 1<<20; }
    }
    __syncthreads();
    for (int k=2; k<=1024; k<<=1){
        for (int j=k>>1; j>0; j>>=1){
            for (int i=threadIdx.x; i<1024; i+=256){
                int ixj = i ^ j;
                if (ixj > i){
                    float vi=v[i], vj=v[ixj]; int ii=id[i], ij=id[ixj];
                    bool before = (vi > vj) || (vi == vj && ii < ij);
                    bool dir = ((i & k) == 0);
                    if (before != dir){ v[i]=vj; v[ixj]=vi; id[i]=ij; id[ixj]=ii; }
                }
            }
            __syncthreads();
        }
    }
    for (int j=threadIdx.x; j<MAXR; j+=256){
        topidx[b*MAXR + j]   = id[j];
        keyvalid[b*MAXR + j] = (v[j] >= 0.5f) ? 1 : 0;
    }
    if (threadIdx.x==0) anyvalid[b] = (v[0] >= 0.5f) ? 1 : 0;
}

__global__ void gather_kernel(const float* __restrict__ retrieved, const int* __restrict__ topidx,
                              float* __restrict__ sel){
    int b = blockIdx.y, j = blockIdx.x;
    int c = topidx[b*MAXR + j];
    int r = c >> 8, k = c & 255;
    const float* src = retrieved + (((long long)(r*BQ + b))*KKC + k)*DIMD;
    float* dst = sel + ((long long)(b*MAXR + j))*DIMD;
    for (int d=threadIdx.x; d<DIMD; d+=256) dst[d] = src[d];
}

__global__ void attn_softmax_kernel(float* __restrict__ att, const int* __restrict__ keyvalid){
    int s = blockIdx.x, h = blockIdx.y, b = blockIdx.z;
    float* p = att + ((((long long)b*NH + h)*SEQ) + s)*MAXR;
    int t = threadIdx.x;
    float val = p[t];
    if (!keyvalid[b*MAXR + t]) val = -1e9f;
    float m = bmax(val);
    float e = __expf(val - m);
    float z = bsum(e);
    p[t] = e / z;
}

__global__ void final_kernel(const float* __restrict__ x, const float* __restrict__ fused,
                             const float* __restrict__ g, const float* __restrict__ bb,
                             const int* __restrict__ anyvalid, float* __restrict__ out){
    long long row = blockIdx.x;
    int b = (int)(row >> 11);
    const float* xp = x + row*DIMD;
    const float* fp = fused + row*DIMD;
    float* op = out + row*DIMD;
    bool any = anyvalid[b] != 0;
    float yv[4]; float s = 0.f;
    #pragma unroll
    for (int i=0;i<4;i++){ int idx = threadIdx.x + i*256; yv[i] = xp[idx] + fp[idx]; s += yv[i]; }
    float mean = bsum(s)*(1.0f/DIMD);
    float v = 0.f;
    #pragma unroll
    for (int i=0;i<4;i++){ float d = yv[i]-mean; v += d*d; }
    float var = bsum(v)*(1.0f/DIMD);
    float rs = rsqrtf(var + 1e-5f);
    #pragma unroll
    for (int i=0;i<4;i++){
        int idx = threadIdx.x + i*256;
        op[idx] = any ? ((yv[i]-mean)*rs*g[idx] + bb[idx]) : xp[idx];
    }
}

// ---------------- host wrappers ----------------
static void gemm(const float* A, const float* B, const float* bias, float* C,
                 int M, int N, int K, int lda, int ldb, int ldc,
                 int nb, long long sA1, long long sB1, long long sC1, long long sBias1,
                 int b2, long long sA2, long long sB2, long long sC2,
                 float alpha, int transB, int act)
{
    dim3 grid((N+TN-1)/TN, (M+TM-1)/TM, nb);
    gemm_kernel<<<grid, 256>>>(A,B,bias,C,M,N,K,lda,ldb,ldc,
                               sA1,sB1,sC1,sBias1,b2,sA2,sB2,sC2,alpha,transB,act);
}

static void hgemm(const __nv_bfloat16* Ah, const __nv_bfloat16* Al,
                  const __nv_bfloat16* Bh, const __nv_bfloat16* Bl,
                  const float* bias, float* Cf, __nv_bfloat16* Chi, __nv_bfloat16* Clo,
                  int M, int N, int K, int lda, int ldb, int ldc,
                  int nb, long long sA, long long sB, long long sC, long long sBias,
                  float alpha, int act)
{
    dim3 grid(N/128, M/128, nb);
    hgemm_kernel<<<grid, 256>>>(Ah,Al,Bh,Bl,bias,Cf,Chi,Clo,
                                M,N,K,lda,ldb,ldc,sA,sB,sC,sBias,alpha,act);
}

extern "C" void kernel_launch(void* const* d_in, const int* in_sizes, int n_in,
                              void* d_out, int out_size)
{
    const float* x       = (const float*)d_in[0];
    const float* retr    = (const float*)d_in[1];
    const float* qg_w1   = (const float*)d_in[2];
    const float* qg_b1   = (const float*)d_in[3];
    const float* qg_w2   = (const float*)d_in[4];
    const float* qg_b2   = (const float*)d_in[5];
    const float* pln_g   = (const float*)d_in[6];
    const float* pln_b   = (const float*)d_in[7];
    const float* pool_w  = (const float*)d_in[8];
    const float* pool_b  = (const float*)d_in[9];
    const float* rel_w1  = (const float*)d_in[10];
    const float* rel_b1  = (const float*)d_in[11];
    const float* rel_w2  = (const float*)d_in[12];
    const float* rel_b2  = (const float*)d_in[13];
    const float* in_w    = (const float*)d_in[14];
    const float* in_b    = (const float*)d_in[15];
    const float* out_w   = (const float*)d_in[16];
    const float* out_b   = (const float*)d_in[17];
    const float* fln_g   = (const float*)d_in[18];
    const float* fln_b   = (const float*)d_in[19];

    float* S = nullptr;
    cudaGetSymbolAddress((void**)&S, g_scratch);
    int *TI=nullptr, *KV=nullptr, *AV=nullptr;
    cudaGetSymbolAddress((void**)&TI, g_topidx);
    cudaGetSymbolAddress((void**)&KV, g_keyvalid);
    cudaGetSymbolAddress((void**)&AV, g_anyvalid);

    __nv_bfloat16 *XH,*XL,*W1TH,*W1TL,*W2TH,*W2TL,*IW0H,*IW0L,*OWH,*OWL,*HH,*HL,*QFH,*QFL,*AOH,*AOL;
    cudaGetSymbolAddress((void**)&XH, g_xh);    cudaGetSymbolAddress((void**)&XL, g_xl);
    cudaGetSymbolAddress((void**)&W1TH, g_w1th); cudaGetSymbolAddress((void**)&W1TL, g_w1tl);
    cudaGetSymbolAddress((void**)&W2TH, g_w2th); cudaGetSymbolAddress((void**)&W2TL, g_w2tl);
    cudaGetSymbolAddress((void**)&IW0H, g_inw0th); cudaGetSymbolAddress((void**)&IW0L, g_inw0tl);
    cudaGetSymbolAddress((void**)&OWH, g_outwth); cudaGetSymbolAddress((void**)&OWL, g_outwtl);
    cudaGetSymbolAddress((void**)&HH, g_Hh);     cudaGetSymbolAddress((void**)&HL, g_Hl);
    cudaGetSymbolAddress((void**)&QFH, g_QFh);   cudaGetSymbolAddress((void**)&QFL, g_QFl);
    cudaGetSymbolAddress((void**)&AOH, g_AOh);   cudaGetSymbolAddress((void**)&AOL, g_AOl);

    float* QF     = S + OFF_QF;
    float* SC     = S + OFF_SC;
    float* QP     = S + OFF_QP;
    float* AO     = S + OFF_AO;
    float* FUSED  = S + OFF_FUSED;
    float* ATT    = S + OFF_ATT;
    float* HBUF   = S + OFF_HBUF;
    float* SEL    = S + OFF_SEL;
    float* KP     = S + OFF_KP;
    float* VP     = S + OFF_VP;
    float* RINV   = S + OFF_RINV;
    float* WCOL   = S + OFF_W;
    float* POOLED = S + OFF_POOLED;
    float* PLN    = S + OFF_PLN;
    float* QUER   = S + OFF_QUER;
    float* QC     = S + OFF_QC;
    float* REL    = S + OFF_REL;

    const int MS = BQ*SEQ;  // 8192
    const long long MD = (long long)MS*DIMD;
    const long long DD = (long long)DIMD*DIMD;

    // ---- conversions ----
    split_kernel<<<(int)(MD/256), 256>>>(x, XH, XL, (int)MD);
    tsplit_kernel<<<dim3(32,32,RR), dim3(32,8)>>>(qg_w1, W1TH, W1TL, DIMD, DIMD);
    tsplit_kernel<<<dim3(32,32,RR), dim3(32,8)>>>(qg_w2, W2TH, W2TL, DIMD, DIMD);
    tsplit_kernel<<<dim3(32,32,1),  dim3(32,8)>>>(in_w,  IW0H, IW0L, DIMD, DIMD);
    tsplit_kernel<<<dim3(32,32,1),  dim3(32,8)>>>(out_w, OWH,  OWL,  DIMD, DIMD);

    // ---- Stage A: query-gen MLPs on HMMA ----
    hgemm(XH, XL, W1TH, W1TL, qg_b1, nullptr, HH, HL,
          MS, DIMD, DIMD, DIMD, DIMD, DIMD,
          RR, 0, DD, MD, DIMD, 1.0f, 1);
    hgemm(HH, HL, W2TH, W2TL, qg_b2, QF, QFH, QFL,
          MS, DIMD, DIMD, DIMD, DIMD, DIMD,
          RR, MD, DD, MD, DIMD, 1.0f, 0);

    // ---- Stage B: pooling scores = QF @ QF^T / 32 on HMMA ----
    hgemm(QFH, QFL, QFH, QFL, nullptr, SC, nullptr, nullptr,
          SEQ, SEQ, DIMD, DIMD, DIMD, SEQ,
          RR*BQ, (long long)SEQ*DIMD, (long long)SEQ*DIMD, (long long)SEQ*SEQ, 0,
          1.0f/32.0f, 0);

    // ---- Stage C: row softmax (in place) + column weights ----
    softmax_rows_kernel<<<RR*BQ*SEQ, 256>>>(SC, RINV);
    colw_kernel<<<dim3(SEQ/128, RR*BQ), 128>>>(SC, RINV, WCOL);

    // ---- Stage D: pooled -> LN -> queries ----
    pooled_kernel<<<dim3(DIMD/256, RR*BQ), 256>>>(QF, WCOL, POOLED);
    lnvec_kernel<<<RR*BQ, 256>>>(POOLED, pln_g, pln_b, PLN);
    gemv_rb_kernel<<<dim3(DIMD/256, RR*BQ), 256>>>(PLN, pool_w, pool_b, QUER,
                                                   DIMD, 0, (long long)DIMD*DIMD, DIMD);

    // ---- Stage E: relevance scores ----
    gemv_rb_kernel<<<dim3(512/256, RR*BQ), 256>>>(QUER, rel_w1, rel_b1, QC,
                                                  512, DIMD, 0LL, 0);
    gemm(retr, rel_w1, nullptr, HBUF,
         RR*BQ*KKC, 512, DIMD, DIMD, 512, 512,
         1, 0,0,0, 0, 1, 0,0,0, 1.0f, 0, 0);
    rel_kernel<<<RR*BQ*KKC, 256>>>(HBUF, QC, rel_w2, rel_b2, REL);

    // ---- Stage F: threshold + top-k + gather ----
    topk_kernel<<<BQ, 256>>>(REL, TI, KV, AV);
    gather_kernel<<<dim3(MAXR, BQ), 256>>>(retr, TI, SEL);

    // ---- Stage G: fusion cross-attention ----
    hgemm(XH, XL, IW0H, IW0L, in_b, QP, nullptr, nullptr,
          MS, DIMD, DIMD, DIMD, DIMD, DIMD,
          1, 0, 0, 0, 0, 1.0f, 0);
    gemm(SEL, in_w + (size_t)DIMD*DIMD,   in_b + DIMD,   KP, BQ*MAXR, DIMD, DIMD, DIMD, DIMD, DIMD,
         1, 0,0,0, 0, 1, 0,0,0, 1.0f, 0, 0);
    gemm(SEL, in_w + (size_t)2*DIMD*DIMD, in_b + 2*DIMD, VP, BQ*MAXR, DIMD, DIMD, DIMD, DIMD, DIMD,
         1, 0,0,0, 0, 1, 0,0,0, 1.0f, 0, 0);

    gemm(QP, KP, nullptr, ATT,
         SEQ, MAXR, HDIM, DIMD, DIMD, MAXR,
         BQ*NH, (long long)SEQ*DIMD, (long long)MAXR*DIMD, (long long)NH*SEQ*MAXR, 0,
         NH, HDIM, HDIM, (long long)SEQ*MAXR,
         0.08838834764831845f, 1, 0);

    attn_softmax_kernel<<<dim3(SEQ, NH, BQ), 256>>>(ATT, KV);

    gemm(ATT, VP, nullptr, AO,
         SEQ, HDIM, MAXR, MAXR, DIMD, DIMD,
         BQ*NH, (long long)NH*SEQ*MAXR, (long long)MAXR*DIMD, (long long)SEQ*DIMD, 0,
         NH, (long long)SEQ*MAXR, HDIM, HDIM,
         1.0f, 0, 0);

    split_kernel<<<(int)(MD/256), 256>>>(AO, AOH, AOL, (int)MD);
    hgemm(AOH, AOL, OWH, OWL, out_b, FUSED, nullptr, nullptr,
          MS, DIMD, DIMD, DIMD, DIMD, DIMD,
          1, 0, 0, 0, 0, 1.0f, 0);

    final_kernel<<<MS, 256>>>(x, FUSED, fln_g, fln_b, AV, (float*)d_out);
}